// round 4
// baseline (speedup 1.0000x reference)
#include <cuda_runtime.h>
#include <cuda_bf16.h>

#define TPB 256
#define ROWF 52      // per-point staged floats: 3 means + 3 dc + 45 rest + 1 opac
#define STRIDE 53    // padded smem row stride (odd -> conflict-free LDS)

__device__ __forceinline__ float gather_elem(
    const float* __restrict__ means,
    const float* __restrict__ fdc,
    const float* __restrict__ frest,
    const float* __restrict__ opac,
    unsigned idx, unsigned j)
{
    if (j < 3u)       return __ldg(&means[idx * 3u + j]);
    else if (j < 6u)  return __ldg(&fdc[idx * 3u + (j - 3u)]);
    else if (j < 51u) return __ldg(&frest[idx * 45u + (j - 6u)]);
    else              return __ldg(&opac[idx]);
}

__global__ __launch_bounds__(TPB)
void VanillaGaussianFieldHead_kernel(
    const float* __restrict__ means,
    const float* __restrict__ fdc,
    const float* __restrict__ frest,
    const float* __restrict__ opac,
    const float* __restrict__ c2w,
    const int*   __restrict__ midx,
    const int*   __restrict__ stepp,
    float*       __restrict__ out,
    int M)
{
    extern __shared__ float smem[];
    float* sf   = smem;                          // TPB * STRIDE floats
    int*   sidx = (int*)(smem + TPB * STRIDE);   // TPB ints

    const int t = threadIdx.x;
    const int base = blockIdx.x * TPB;
    const int p_global = base + t;

    // Stage mask indices (coalesced)
    sidx[t] = (p_global < M) ? midx[p_global] : 0;
    __syncthreads();

    // Phase 1: cooperative coalesced gather of ALL per-point data into smem.
    // Linear element order: consecutive lanes walk consecutive addresses
    // within each (random) row -> ~2-3 L1tex wavefronts per point instead of
    // ~130 for per-thread scattered loads.
    const int nvalid = min(TPB, M - base);
    if (nvalid == TPB) {
        // Fast path (all blocks except possibly the last): fixed trip count,
        // lets ptxas batch independent LDGs for high MLP.
        #pragma unroll 4
        for (int it = 0; it < ROWF; it++) {
            const unsigned e = (unsigned)(it * TPB + t);
            const unsigned p = e / ROWF;
            const unsigned j = e - p * ROWF;
            const unsigned idx = (unsigned)sidx[p];
            sf[p * STRIDE + j] = gather_elem(means, fdc, frest, opac, idx, j);
        }
    } else {
        const int total = nvalid * ROWF;
        for (int e = t; e < total; e += TPB) {
            const unsigned p = (unsigned)e / ROWF;
            const unsigned j = (unsigned)e - p * ROWF;
            const unsigned idx = (unsigned)sidx[p];
            sf[p * STRIDE + j] = gather_elem(means, fdc, frest, opac, idx, j);
        }
    }
    __syncthreads();

    if (p_global >= M) return;

    const float* row = sf + t * STRIDE;

    // View direction (means come from smem)
    const float cx = c2w[3], cy = c2w[7], cz = c2w[11];
    float x = row[0] - cx;
    float y = row[1] - cy;
    float z = row[2] - cz;
    const float inv = rsqrtf(x * x + y * y + z * z);
    x *= inv; y *= inv; z *= inv;

    const int n = min(stepp[0] / 1000, 3);

    float b[16];
    b[0] = 0.28209479177387814f;
    int kmax = 1;
    const float xx = x * x, yy = y * y, zz = z * z;
    if (n >= 1) {
        const float C1 = 0.4886025119029199f;
        b[1] = -C1 * y;
        b[2] =  C1 * z;
        b[3] = -C1 * x;
        kmax = 4;
    }
    if (n >= 2) {
        b[4] =  1.0925484305920792f * (x * y);
        b[5] = -1.0925484305920792f * (y * z);
        b[6] =  0.31539156525252005f * (2.0f * zz - xx - yy);
        b[7] = -1.0925484305920792f * (x * z);
        b[8] =  0.5462742152960396f * (xx - yy);
        kmax = 9;
    }
    if (n >= 3) {
        b[9]  = -0.5900435899266435f * y * (3.0f * xx - yy);
        b[10] =  2.890611442640554f  * (x * y) * z;
        b[11] = -0.4570457994644658f * y * (4.0f * zz - xx - yy);
        b[12] =  0.3731763325901154f * z * (2.0f * zz - 3.0f * xx - 3.0f * yy);
        b[13] = -0.4570457994644658f * x * (4.0f * zz - xx - yy);
        b[14] =  1.445305721320277f  * z * (xx - yy);
        b[15] = -0.5900435899266435f * x * (xx - 3.0f * yy);
        kmax = 16;
    }

    // Dot products: feats live at row[3 + 3k + c] (after the 3 means floats).
    float r = 0.0f, g = 0.0f, bch = 0.0f;
    #pragma unroll 16
    for (int k = 0; k < 16; k++) {
        if (k >= kmax) break;   // kmax is warp-uniform (branch on uniform n)
        const float w = b[k];
        r   = fmaf(w, row[3 + 3 * k + 0], r);
        g   = fmaf(w, row[3 + 3 * k + 1], g);
        bch = fmaf(w, row[3 + 3 * k + 2], bch);
    }

    r   = fmaxf(r   + 0.5f, 0.0f);
    g   = fmaxf(g   + 0.5f, 0.0f);
    bch = fmaxf(bch + 0.5f, 0.0f);

    out[3 * (size_t)p_global + 0] = r;
    out[3 * (size_t)p_global + 1] = g;
    out[3 * (size_t)p_global + 2] = bch;
    out[3 * (size_t)M + p_global] = row[51];   // opacity
}

extern "C" void kernel_launch(void* const* d_in, const int* in_sizes, int n_in,
                              void* d_out, int out_size) {
    const float* means = (const float*)d_in[0];
    const float* fdc   = (const float*)d_in[1];
    const float* frest = (const float*)d_in[2];
    const float* opac  = (const float*)d_in[3];
    const float* c2w   = (const float*)d_in[4];
    const int*   midx  = (const int*)d_in[5];
    const int*   stepp = (const int*)d_in[6];
    float* out = (float*)d_out;

    const int M = in_sizes[5];
    const int smem_bytes = (TPB * STRIDE + TPB) * sizeof(float);

    // Idempotent, graph-capture-safe (not a stream op); needed since
    // smem_bytes (~55 KB) exceeds the 48 KB default opt-in limit.
    cudaFuncSetAttribute(VanillaGaussianFieldHead_kernel,
                         cudaFuncAttributeMaxDynamicSharedMemorySize, smem_bytes);

    const int blocks = (M + TPB - 1) / TPB;
    VanillaGaussianFieldHead_kernel<<<blocks, TPB, smem_bytes>>>(
        means, fdc, frest, opac, c2w, midx, stepp, out, M);
}

// round 5
// speedup vs baseline: 1.5116x; 1.5116x over previous
#include <cuda_runtime.h>
#include <cuda_bf16.h>
#include <cstdint>

#define TPB 128
#define STRIDE 53    // padded smem row stride (odd -> conflict-free LDS)
// Row layout per point: [0:3) means, [3:6) dc, [6:51) rest, [51] opac

__device__ __forceinline__ uint32_t smem_u32(const void* p) {
    return (uint32_t)__cvta_generic_to_shared(p);
}
__device__ __forceinline__ void cp4(uint32_t dst, const float* __restrict__ src) {
    asm volatile("cp.async.ca.shared.global [%0], [%1], 4;" :: "r"(dst), "l"(src));
}

__global__ __launch_bounds__(TPB)
void VanillaGaussianFieldHead_kernel(
    const float* __restrict__ means,
    const float* __restrict__ fdc,
    const float* __restrict__ frest,
    const float* __restrict__ opac,
    const float* __restrict__ c2w,
    const int*   __restrict__ midx,
    const int*   __restrict__ stepp,
    float*       __restrict__ out,
    int M)
{
    extern __shared__ float smem[];
    float* sf   = smem;                          // TPB * STRIDE floats
    int*   sidx = (int*)(smem + TPB * STRIDE);   // TPB ints

    const int t = threadIdx.x;
    const int base = blockIdx.x * TPB;
    const int p_global = base + t;

    sidx[t] = (p_global < M) ? midx[p_global] : 0;
    __syncthreads();

    const int nvalid = min(TPB, M - base);
    const uint32_t sfb = smem_u32(sf);

    if (nvalid == TPB) {
        // Branch-free, fully unrolled cp.async gather: every load is
        // fire-and-forget (no dest register, no scoreboard dep) -> all ~52
        // loads per thread in flight simultaneously. Consecutive threads walk
        // consecutive addresses within each (random) row -> coalesced.
        #pragma unroll
        for (int it = 0; it < 45; it++) {               // rest: 45 floats/point
            const unsigned e = (unsigned)(it * TPB + t);
            const unsigned p = e / 45u;
            const unsigned j = e - p * 45u;
            const unsigned idx = (unsigned)sidx[p];
            cp4(sfb + (p * STRIDE + 6u + j) * 4u, frest + (size_t)idx * 45u + j);
        }
        #pragma unroll
        for (int it = 0; it < 3; it++) {                // dc: 3 floats/point
            const unsigned e = (unsigned)(it * TPB + t);
            const unsigned p = e / 3u;
            const unsigned j = e - p * 3u;
            const unsigned idx = (unsigned)sidx[p];
            cp4(sfb + (p * STRIDE + 3u + j) * 4u, fdc + (size_t)idx * 3u + j);
        }
        #pragma unroll
        for (int it = 0; it < 3; it++) {                // means: 3 floats/point
            const unsigned e = (unsigned)(it * TPB + t);
            const unsigned p = e / 3u;
            const unsigned j = e - p * 3u;
            const unsigned idx = (unsigned)sidx[p];
            cp4(sfb + (p * STRIDE + j) * 4u, means + (size_t)idx * 3u + j);
        }
        {                                                // opac: 1 float/point
            const unsigned idx = (unsigned)sidx[t];
            cp4(sfb + ((unsigned)t * STRIDE + 51u) * 4u, opac + idx);
        }
    } else {
        // Tail block (at most one per grid): guarded cp.async, same layout.
        const unsigned tot45 = (unsigned)nvalid * 45u;
        for (unsigned e = t; e < tot45; e += TPB) {
            const unsigned p = e / 45u, j = e - p * 45u;
            const unsigned idx = (unsigned)sidx[p];
            cp4(sfb + (p * STRIDE + 6u + j) * 4u, frest + (size_t)idx * 45u + j);
        }
        const unsigned tot3 = (unsigned)nvalid * 3u;
        for (unsigned e = t; e < tot3; e += TPB) {
            const unsigned p = e / 3u, j = e - p * 3u;
            const unsigned idx = (unsigned)sidx[p];
            cp4(sfb + (p * STRIDE + 3u + j) * 4u, fdc + (size_t)idx * 3u + j);
            cp4(sfb + (p * STRIDE + j) * 4u,      means + (size_t)idx * 3u + j);
        }
        if (t < nvalid) {
            const unsigned idx = (unsigned)sidx[t];
            cp4(sfb + ((unsigned)t * STRIDE + 51u) * 4u, opac + idx);
        }
    }

    asm volatile("cp.async.commit_group;\ncp.async.wait_group 0;" ::: "memory");
    __syncthreads();

    if (p_global >= M) return;

    const float* row = sf + t * STRIDE;

    // View direction
    const float cx = c2w[3], cy = c2w[7], cz = c2w[11];
    float x = row[0] - cx;
    float y = row[1] - cy;
    float z = row[2] - cz;
    const float inv = rsqrtf(x * x + y * y + z * z);
    x *= inv; y *= inv; z *= inv;

    const int n = min(stepp[0] / 1000, 3);

    float b[16];
    b[0] = 0.28209479177387814f;
    int kmax = 1;
    const float xx = x * x, yy = y * y, zz = z * z;
    if (n >= 1) {
        const float C1 = 0.4886025119029199f;
        b[1] = -C1 * y;
        b[2] =  C1 * z;
        b[3] = -C1 * x;
        kmax = 4;
    }
    if (n >= 2) {
        b[4] =  1.0925484305920792f * (x * y);
        b[5] = -1.0925484305920792f * (y * z);
        b[6] =  0.31539156525252005f * (2.0f * zz - xx - yy);
        b[7] = -1.0925484305920792f * (x * z);
        b[8] =  0.5462742152960396f * (xx - yy);
        kmax = 9;
    }
    if (n >= 3) {
        b[9]  = -0.5900435899266435f * y * (3.0f * xx - yy);
        b[10] =  2.890611442640554f  * (x * y) * z;
        b[11] = -0.4570457994644658f * y * (4.0f * zz - xx - yy);
        b[12] =  0.3731763325901154f * z * (2.0f * zz - 3.0f * xx - 3.0f * yy);
        b[13] = -0.4570457994644658f * x * (4.0f * zz - xx - yy);
        b[14] =  1.445305721320277f  * z * (xx - yy);
        b[15] = -0.5900435899266435f * x * (xx - 3.0f * yy);
        kmax = 16;
    }

    float r = 0.0f, g = 0.0f, bch = 0.0f;
    #pragma unroll 16
    for (int k = 0; k < 16; k++) {
        if (k >= kmax) break;   // kmax is warp-uniform
        const float w = b[k];
        r   = fmaf(w, row[3 + 3 * k + 0], r);
        g   = fmaf(w, row[3 + 3 * k + 1], g);
        bch = fmaf(w, row[3 + 3 * k + 2], bch);
    }

    r   = fmaxf(r   + 0.5f, 0.0f);
    g   = fmaxf(g   + 0.5f, 0.0f);
    bch = fmaxf(bch + 0.5f, 0.0f);

    out[3 * (size_t)p_global + 0] = r;
    out[3 * (size_t)p_global + 1] = g;
    out[3 * (size_t)p_global + 2] = bch;
    out[3 * (size_t)M + p_global] = row[51];   // opacity
}

extern "C" void kernel_launch(void* const* d_in, const int* in_sizes, int n_in,
                              void* d_out, int out_size) {
    const float* means = (const float*)d_in[0];
    const float* fdc   = (const float*)d_in[1];
    const float* frest = (const float*)d_in[2];
    const float* opac  = (const float*)d_in[3];
    const float* c2w   = (const float*)d_in[4];
    const int*   midx  = (const int*)d_in[5];
    const int*   stepp = (const int*)d_in[6];
    float* out = (float*)d_out;

    const int M = in_sizes[5];
    const int smem_bytes = (TPB * STRIDE + TPB) * sizeof(float);

    cudaFuncSetAttribute(VanillaGaussianFieldHead_kernel,
                         cudaFuncAttributeMaxDynamicSharedMemorySize, smem_bytes);

    const int blocks = (M + TPB - 1) / TPB;
    VanillaGaussianFieldHead_kernel<<<blocks, TPB, smem_bytes>>>(
        means, fdc, frest, opac, c2w, midx, stepp, out, M);
}

// round 8
// speedup vs baseline: 1.5483x; 1.0243x over previous
#include <cuda_runtime.h>
#include <cuda_bf16.h>
#include <cstdint>

#define TPB 128
#define STRIDE 53      // padded smem row stride (odd -> conflict-free LDS)
#define NIDX 3         // index-buffer ring depth
// Row layout per point: [0:3) means, [3:6) dc, [6:51) rest, [51] opac

__device__ __forceinline__ uint32_t smem_u32(const void* p) {
    return (uint32_t)__cvta_generic_to_shared(p);
}
__device__ __forceinline__ void cp4(uint32_t dst, const void* __restrict__ src) {
    asm volatile("cp.async.ca.shared.global [%0], [%1], 4;" :: "r"(dst), "l"(src));
}
__device__ __forceinline__ void commit_group() {
    asm volatile("cp.async.commit_group;" ::: "memory");
}

__global__ __launch_bounds__(TPB)
void VanillaGaussianFieldHead_kernel(
    const float* __restrict__ means,
    const float* __restrict__ fdc,
    const float* __restrict__ frest,
    const float* __restrict__ opac,
    const float* __restrict__ c2w,
    const int*   __restrict__ midx,
    const int*   __restrict__ stepp,
    float*       __restrict__ out,
    int M, int ntiles, int tilesPerCta)
{
    extern __shared__ float smem[];
    float* sf   = smem;                             // 2 * TPB * STRIDE floats
    int*   sidx = (int*)(smem + 2 * TPB * STRIDE);  // NIDX * TPB ints

    const int t = threadIdx.x;
    const int tile0 = blockIdx.x * tilesPerCta;
    const int K = min(tile0 + tilesPerCta, ntiles) - tile0;
    if (K <= 0) return;   // uniform block exit, no barriers executed

    const uint32_t sfb = smem_u32(sf);
    const uint32_t sib = smem_u32(sidx);

    // ---- async issue helpers (all-thread, guards inside) ----
    auto issue_idx = [&](int j) {   // prefetch mask indices for tile j
        if (j < K) {
            const int g = (tile0 + j) * TPB + t;
            if (g < M) cp4(sib + (uint32_t)((j % NIDX) * TPB + t) * 4u, midx + g);
        }
    };
    auto issue_data = [&](int j) {  // gather all per-point data for tile j
        if (j >= K) return;
        const int* __restrict__ sid = sidx + (j % NIDX) * TPB;
        const uint32_t buf = sfb + (uint32_t)((j & 1) * TPB * STRIDE) * 4u;
        const int base = (tile0 + j) * TPB;
        const int nv = min(TPB, M - base);
        if (nv == TPB) {
            #pragma unroll
            for (int it = 0; it < 45; it++) {           // rest: 45 floats/point
                const unsigned e = (unsigned)(it * TPB + t);
                const unsigned p = e / 45u, jj = e - p * 45u;
                const unsigned idx = (unsigned)sid[p];
                cp4(buf + (p * STRIDE + 6u + jj) * 4u, frest + (size_t)idx * 45u + jj);
            }
            #pragma unroll
            for (int it = 0; it < 3; it++) {            // dc + means: 3 each
                const unsigned e = (unsigned)(it * TPB + t);
                const unsigned p = e / 3u, jj = e - p * 3u;
                const unsigned idx = (unsigned)sid[p];
                cp4(buf + (p * STRIDE + 3u + jj) * 4u, fdc   + (size_t)idx * 3u + jj);
                cp4(buf + (p * STRIDE + jj) * 4u,      means + (size_t)idx * 3u + jj);
            }
            {                                            // opac: 1 float/point
                const unsigned idx = (unsigned)sid[t];
                cp4(buf + ((unsigned)t * STRIDE + 51u) * 4u, opac + idx);
            }
        } else {                                         // partial tail tile
            const unsigned tot45 = (unsigned)nv * 45u;
            for (unsigned e = t; e < tot45; e += TPB) {
                const unsigned p = e / 45u, jj = e - p * 45u;
                const unsigned idx = (unsigned)sid[p];
                cp4(buf + (p * STRIDE + 6u + jj) * 4u, frest + (size_t)idx * 45u + jj);
            }
            const unsigned tot3 = (unsigned)nv * 3u;
            for (unsigned e = t; e < tot3; e += TPB) {
                const unsigned p = e / 3u, jj = e - p * 3u;
                const unsigned idx = (unsigned)sid[p];
                cp4(buf + (p * STRIDE + 3u + jj) * 4u, fdc   + (size_t)idx * 3u + jj);
                cp4(buf + (p * STRIDE + jj) * 4u,      means + (size_t)idx * 3u + jj);
            }
            if (t < nv) {
                const unsigned idx = (unsigned)sid[t];
                cp4(buf + ((unsigned)t * STRIDE + 51u) * 4u, opac + idx);
            }
        }
    };

    // ---- uniforms ----
    const float cx = __ldg(&c2w[3]), cy = __ldg(&c2w[7]), cz = __ldg(&c2w[11]);
    const int n = min(stepp[0] / 1000, 3);

    // ---- pipeline prologue ----
    issue_idx(0); issue_idx(1);
    commit_group();
    asm volatile("cp.async.wait_group 0;" ::: "memory");
    __syncthreads();                 // idx(0), idx(1) visible to all
    issue_data(0); issue_idx(2);
    commit_group();                  // C_0 = { data0, idx2 }
    __syncthreads();                 // reads of idx slot0 done before iter0 rewrites it

    // ---- steady-state loop ----
    for (int i = 0; i < K; i++) {
        issue_data(i + 1);           // uses idx(i+1): arrived in C_{i-1} (or prologue)
        issue_idx(i + 3);            // writes slot i%NIDX (idx(i) is dead)
        commit_group();              // C_{i+1} (possibly empty near tail)
        asm volatile("cp.async.wait_group 1;" ::: "memory");  // C_i done
        __syncthreads();             // data(i) + idx(i+2) visible to all

        const int p_global = (tile0 + i) * TPB + t;
        if (p_global < M) {
            const float* row = sf + ((i & 1) * TPB + t) * STRIDE;

            float x = row[0] - cx;
            float y = row[1] - cy;
            float z = row[2] - cz;
            const float inv = rsqrtf(x * x + y * y + z * z);
            x *= inv; y *= inv; z *= inv;

            float b[16];
            b[0] = 0.28209479177387814f;
            int kmax = 1;
            const float xx = x * x, yy = y * y, zz = z * z;
            if (n >= 1) {
                const float C1 = 0.4886025119029199f;
                b[1] = -C1 * y; b[2] = C1 * z; b[3] = -C1 * x;
                kmax = 4;
            }
            if (n >= 2) {
                b[4] =  1.0925484305920792f * (x * y);
                b[5] = -1.0925484305920792f * (y * z);
                b[6] =  0.31539156525252005f * (2.0f * zz - xx - yy);
                b[7] = -1.0925484305920792f * (x * z);
                b[8] =  0.5462742152960396f * (xx - yy);
                kmax = 9;
            }
            if (n >= 3) {
                b[9]  = -0.5900435899266435f * y * (3.0f * xx - yy);
                b[10] =  2.890611442640554f  * (x * y) * z;
                b[11] = -0.4570457994644658f * y * (4.0f * zz - xx - yy);
                b[12] =  0.3731763325901154f * z * (2.0f * zz - 3.0f * xx - 3.0f * yy);
                b[13] = -0.4570457994644658f * x * (4.0f * zz - xx - yy);
                b[14] =  1.445305721320277f  * z * (xx - yy);
                b[15] = -0.5900435899266435f * x * (xx - 3.0f * yy);
                kmax = 16;
            }

            float r = 0.0f, g = 0.0f, bch = 0.0f;
            #pragma unroll 16
            for (int k = 0; k < 16; k++) {
                if (k >= kmax) break;   // warp-uniform
                const float w = b[k];
                r   = fmaf(w, row[3 + 3 * k + 0], r);
                g   = fmaf(w, row[3 + 3 * k + 1], g);
                bch = fmaf(w, row[3 + 3 * k + 2], bch);
            }

            out[3 * (size_t)p_global + 0] = fmaxf(r   + 0.5f, 0.0f);
            out[3 * (size_t)p_global + 1] = fmaxf(g   + 0.5f, 0.0f);
            out[3 * (size_t)p_global + 2] = fmaxf(bch + 0.5f, 0.0f);
            out[3 * (size_t)M + p_global] = row[51];   // opacity
        }
        __syncthreads();             // compute(i) done before data(i+2) overwrites buf i&1
    }
}

extern "C" void kernel_launch(void* const* d_in, const int* in_sizes, int n_in,
                              void* d_out, int out_size) {
    const float* means = (const float*)d_in[0];
    const float* fdc   = (const float*)d_in[1];
    const float* frest = (const float*)d_in[2];
    const float* opac  = (const float*)d_in[3];
    const float* c2w   = (const float*)d_in[4];
    const int*   midx  = (const int*)d_in[5];
    const int*   stepp = (const int*)d_in[6];
    float* out = (float*)d_out;

    const int M = in_sizes[5];
    const int ntiles = (M + TPB - 1) / TPB;
    int grid = 4 * 148;                 // 4 CTAs/SM target (smem-limited)
    if (grid > ntiles) grid = ntiles;
    const int tilesPerCta = (ntiles + grid - 1) / grid;
    grid = (ntiles + tilesPerCta - 1) / tilesPerCta;   // trim empty CTAs

    const int smem_bytes = (2 * TPB * STRIDE) * sizeof(float) + NIDX * TPB * sizeof(int);

    cudaFuncSetAttribute(VanillaGaussianFieldHead_kernel,
                         cudaFuncAttributeMaxDynamicSharedMemorySize, smem_bytes);

    VanillaGaussianFieldHead_kernel<<<grid, TPB, smem_bytes>>>(
        means, fdc, frest, opac, c2w, midx, stepp, out, M, ntiles, tilesPerCta);
}